// round 16
// baseline (speedup 1.0000x reference)
#include <cuda_runtime.h>
#include <cuda_fp16.h>
#include <math.h>
#include <stdint.h>

#define Bn 8
#define CINc 128
#define COUTc 128
#define Hh 64
#define Ww 64
#define HWn 4096
#define KKn 9
#define OFFC 18
#define Kdim 1152            // CIN * KK
#define NPIX 32768           // B * HW
#define TILE_N 64            // pixels per fused-GEMM CTA (2 CTAs/SM)
#define NTILES (NPIX / TILE_N)   // 512
#define NCH64 18             // Kdim / 64
#define SRH 72               // smem row stride in halves (64 + pad 8)

// fused gemm smem: 2 stages of (A 128x72 + B 64x72) halves + meta
#define GA_H (128 * SRH)             // 9216 halves
#define GB_H (64 * SRH)              // 4608
#define GSTG_H (GA_H + GB_H)         // 13824
#define META_BYTES (KKn * TILE_N * 32)  // 18432
#define GEMM_SMEM (2 * GSTG_H * 2 + META_BYTES)   // 73728 B

// offset gemm smem: A 32x72, B 64x72 per stage, 2 stages
#define OA_H (32 * SRH)              // 2304
#define OB_H (64 * SRH)              // 4608
#define OSTG_H (OA_H + OB_H)         // 6912
#define OFF_SMEM (2 * OSTG_H * 2)    // 27648 B

// ---------------- static scratch ----------------
__device__ __half g_xh[Bn * HWn * CINc];     // x NHWC fp16 (8.4 MB)
__device__ float  g_off[Bn * OFFC * HWn];    // offset conv out fp32
__device__ __half g_wtp[NCH64 * 8192];       // w_def packed [ch64][co][64k]
__device__ __half g_woffp[NCH64 * 2048];     // w_off packed [ch64][oc32][64k]
__device__ float  g_psum[COUTc * NTILES];
__device__ float  g_psq [COUTc * NTILES];

// ---------------- helpers ----------------
__device__ __forceinline__ void mma_f16(float* d, const uint32_t* a,
                                        uint32_t b0, uint32_t b1) {
    asm volatile(
        "mma.sync.aligned.m16n8k16.row.col.f32.f16.f16.f32 "
        "{%0,%1,%2,%3}, {%4,%5,%6,%7}, {%8,%9}, {%0,%1,%2,%3};"
        : "+f"(d[0]), "+f"(d[1]), "+f"(d[2]), "+f"(d[3])
        : "r"(a[0]), "r"(a[1]), "r"(a[2]), "r"(a[3]), "r"(b0), "r"(b1));
}
__device__ __forceinline__ void ldsm_x4(uint32_t* r, uint32_t addr) {
    asm volatile("ldmatrix.sync.aligned.m8n8.x4.shared.b16 {%0,%1,%2,%3}, [%4];"
                 : "=r"(r[0]), "=r"(r[1]), "=r"(r[2]), "=r"(r[3]) : "r"(addr));
}
__device__ __forceinline__ void ldsm_x2(uint32_t& r0, uint32_t& r1, uint32_t addr) {
    asm volatile("ldmatrix.sync.aligned.m8n8.x2.shared.b16 {%0,%1}, [%2];"
                 : "=r"(r0), "=r"(r1) : "r"(addr));
}
__device__ __forceinline__ uint32_t s2u(const void* p) {
    return (uint32_t)__cvta_generic_to_shared(p);
}
// pure-fp16 bilinear blend (HMUL2/HFMA2, no cvts)
__device__ __forceinline__ uint32_t blend4h(uint32_t a, uint32_t b,
                                            uint32_t c, uint32_t d,
                                            __half2 w0, __half2 w1,
                                            __half2 w2, __half2 w3) {
    __half2 r = __hmul2(*(__half2*)&a, w0);
    r = __hfma2(*(__half2*)&b, w1, r);
    r = __hfma2(*(__half2*)&c, w2, r);
    r = __hfma2(*(__half2*)&d, w3, r);
    return *(uint32_t*)&r;
}
__device__ __forceinline__ float silu_f(float u) {
    return __fdividef(u, 1.f + __expf(-u));
}

struct __align__(16) MetaF {
    int   i0, i1, i2, i3;
    float w0, w1, w2, w3;
};

// lane offsets for ldmatrix source rows (in BYTES)
#define LANE_OFF_A(lane) ((((lane) & 15) * SRH + (((lane) >> 4) << 3)) * 2)
#define LANE_OFF_B(lane) ((((lane) & 7) * SRH + ((((lane) >> 3) & 1) << 3)) * 2)

// ---------------------------------------------------------------------------
// Kernel 1: merged prep — blocks [0,4096): NCHW->NHWC fp16 transpose,
//           blocks [4096,4816): weight packs
// ---------------------------------------------------------------------------
__global__ __launch_bounds__(256) void k_prep(const float* __restrict__ x,
                                              const float* __restrict__ w_def,
                                              const float* __restrict__ w_off) {
    int bid = blockIdx.x;
    int tid = threadIdx.x;
    if (bid < 4096) {
        __shared__ float tile[32][33];
        int p0 = (bid & 127) * 32;
        int c0 = ((bid >> 7) & 3) * 32;
        int b  = bid >> 9;
        const float* xb = x + (size_t)b * CINc * HWn;
        __half* xtb = g_xh + (size_t)b * HWn * CINc;
        int tx = tid & 31, ty = tid >> 5;
        #pragma unroll
        for (int j = 0; j < 32; j += 8)
            tile[ty + j][tx] = xb[(size_t)(c0 + ty + j) * HWn + p0 + tx];
        __syncthreads();
        #pragma unroll
        for (int m = 0; m < 2; m++) {
            int u = tid + m * 256;
            int pl = u >> 4, cp = u & 15;
            __half2 v = __floats2half2_rn(tile[cp * 2][pl], tile[cp * 2 + 1][pl]);
            *(__half2*)(xtb + (size_t)(p0 + pl) * CINc + c0 + cp * 2) = v;
        }
    } else {
        int idx = (bid - 4096) * 256 + tid;
        if (idx < NCH64 * 8192) {
            int chunk = idx >> 13, r = idx & 8191;
            int co = r >> 6, kloc = r & 63;
            int k = chunk * 64 + kloc;
            int kk = k >> 7, c = k & 127;
            g_wtp[idx] = __float2half(w_def[(size_t)(co * CINc + c) * KKn + kk]);
        } else {
            int j = idx - NCH64 * 8192;
            if (j < NCH64 * 2048) {
                int chunk = j >> 11, r = j & 2047;
                int oc = r >> 6, kloc = r & 63;
                int kk = chunk >> 1, c = (chunk & 1) * 64 + kloc;
                g_woffp[j] = (oc < OFFC)
                    ? __float2half(w_off[(size_t)(oc * CINc + c) * KKn + kk])
                    : __float2half(0.f);
            }
        }
    }
}

// ---------------------------------------------------------------------------
// Kernel 2: offset conv, fp16 implicit GEMM. 512 CTAs (64-pix row tiles),
// 256 thr (8 warps), warp tile 32oc x 8pix, 64-k chunks.
// ---------------------------------------------------------------------------
__global__ __launch_bounds__(256) void k_offset2() {
    extern __shared__ __half smh[];
    const int tid = threadIdx.x;
    const int wid = tid >> 5, lane = tid & 31;
    const int g = lane >> 2, tc = lane & 3;
    const int wn = wid;

    const int tile = blockIdx.x;          // 0..511
    const int b = tile >> 6;
    const int y0 = tile & 63;
    const int hw0 = y0 * 64;
    const __half* xhb = g_xh + (size_t)b * HWn * CINc;

    const uint32_t sbase = s2u(smh);
    const uint32_t laneA = LANE_OFF_A(lane);
    const uint32_t laneB = LANE_OFF_B(lane);

    uint4 bufA;
    uint4 bufB[2];

    float acc[2][4];
    #pragma unroll
    for (int mt = 0; mt < 2; mt++)
        #pragma unroll
        for (int r = 0; r < 4; r++) acc[mt][r] = 0.f;

    auto ldg_chunk = [&](int i) {
        int kk = i >> 1, c0 = (i & 1) * 64;
        int ky = kk / 3 - 1, kx = kk % 3 - 1;
        int ys = y0 + ky;
        bool vy = (unsigned)ys < Hh;
        #pragma unroll
        for (int m = 0; m < 2; m++) {
            int e = tid + m * 256;
            int pix = e >> 3, j = e & 7;
            int xs = pix + kx;
            bool valid = vy && ((unsigned)xs < Ww);
            bufB[m] = valid
                ? *(const uint4*)(xhb + (size_t)(ys * Ww + xs) * CINc + c0 + j * 8)
                : make_uint4(0u, 0u, 0u, 0u);
        }
        bufA = *(const uint4*)(g_woffp + (size_t)i * 2048 + tid * 8);
    };
    auto sts_chunk = [&](int st) {
        __half* As = smh + st * OSTG_H;
        __half* Bs = As + OA_H;
        #pragma unroll
        for (int m = 0; m < 2; m++) {
            int e = tid + m * 256;
            int pix = e >> 3, j = e & 7;
            *(uint4*)(Bs + pix * SRH + j * 8) = bufB[m];
        }
        *(uint4*)(As + (tid >> 3) * SRH + (tid & 7) * 8) = bufA;
    };

    ldg_chunk(0); sts_chunk(0);
    ldg_chunk(1);
    __syncthreads();

    for (int i = 0; i < NCH64; i++) {
        if (i + 1 < NCH64) sts_chunk((i + 1) & 1);
        if (i + 2 < NCH64) ldg_chunk(i + 2);
        const uint32_t aAs = sbase + (uint32_t)((i & 1) * OSTG_H) * 2;
        const uint32_t aBs = aAs + OA_H * 2;
        #pragma unroll
        for (int ks = 0; ks < 4; ks++) {
            uint32_t a[2][4];
            #pragma unroll
            for (int mt = 0; mt < 2; mt++)
                ldsm_x4(a[mt], aAs + (uint32_t)((mt * 16) * SRH + ks * 16) * 2 + laneA);
            uint32_t b0, b1;
            ldsm_x2(b0, b1, aBs + (uint32_t)((wn * 8) * SRH + ks * 16) * 2 + laneB);
            #pragma unroll
            for (int mt = 0; mt < 2; mt++)
                mma_f16(acc[mt], a[mt], b0, b1);
        }
        __syncthreads();
    }

    float* ob = g_off + (size_t)b * OFFC * HWn;
    #pragma unroll
    for (int mt = 0; mt < 2; mt++) {
        int pix = hw0 + wn * 8 + tc * 2;
        int r0 = mt * 16 + g, r1 = r0 + 8;
        if (r0 < OFFC)
            *(float2*)&ob[(size_t)r0 * HWn + pix] = make_float2(acc[mt][0], acc[mt][1]);
        if (r1 < OFFC)
            *(float2*)&ob[(size_t)r1 * HWn + pix] = make_float2(acc[mt][2], acc[mt][3]);
    }
}

// ---------------------------------------------------------------------------
// Kernel 3: FUSED bilinear-gather + fp16 mma GEMM.
// 512 CTAs of 256 threads (8 warps = 2m x 4n), CTA tile 128co x 64pix,
// warp tile 64co x 16pix. 2 CTAs/SM for latency hiding.
// ---------------------------------------------------------------------------
__global__ __launch_bounds__(256, 2) void k_gemm(float* __restrict__ out) {
    extern __shared__ char smraw[];
    __half* smh  = (__half*)smraw;
    MetaF*  meta = (MetaF*)(smraw + 2 * GSTG_H * 2);

    const int tid = threadIdx.x;
    const int wid = tid >> 5, lane = tid & 31;
    const int wm = wid >> 2, wn = wid & 3;
    const int g = lane >> 2, tc = lane & 3;
    const int tilebase = blockIdx.x * TILE_N;
    const int b = tilebase >> 12, hw0 = tilebase & 4095;
    const int ybase = hw0 >> 6;                    // single row per tile
    const __half* xhb = g_xh + (size_t)b * HWn * CINc;

    const uint32_t sbase = s2u(smh);
    const uint32_t laneA = LANE_OFF_A(lane);
    const uint32_t laneB = LANE_OFF_B(lane);

    // ---- phase 0: bilinear metadata (9 kk x 64 pix) ----
    const float* offb = g_off + (size_t)b * OFFC * HWn;
    for (int t = tid; t < KKn * TILE_N; t += 256) {
        int kk = t >> 6, p = t & 63;
        int hw = hw0 + p;
        int xx = hw & 63;
        float dy = offb[(size_t)(kk * 2 + 0) * HWn + hw];
        float dx = offb[(size_t)(kk * 2 + 1) * HWn + hw];
        float ys = (float)(ybase - 1 + kk / 3) + dy;
        float xs = (float)(xx - 1 + kk % 3) + dx;
        float y0f = floorf(ys), x0f = floorf(xs);
        float wy = ys - y0f, wx = xs - x0f;
        int y0 = (int)y0f, x0 = (int)x0f;
        bool vy0 = (y0 >= 0) && (y0 < Hh);
        bool vy1 = (y0 + 1 >= 0) && (y0 + 1 < Hh);
        bool vx0 = (x0 >= 0) && (x0 < Ww);
        bool vx1 = (x0 + 1 >= 0) && (x0 + 1 < Ww);
        MetaF m;
        m.w0 = (vy0 && vx0) ? (1.f - wy) * (1.f - wx) : 0.f;
        m.w1 = (vy0 && vx1) ? (1.f - wy) * wx : 0.f;
        m.w2 = (vy1 && vx0) ? wy * (1.f - wx) : 0.f;
        m.w3 = (vy1 && vx1) ? wy * wx : 0.f;
        m.i0 = (vy0 && vx0) ? (y0 * Ww + x0) * CINc : 0;
        m.i1 = (vy0 && vx1) ? (y0 * Ww + x0 + 1) * CINc : 0;
        m.i2 = (vy1 && vx0) ? ((y0 + 1) * Ww + x0) * CINc : 0;
        m.i3 = (vy1 && vx1) ? ((y0 + 1) * Ww + x0 + 1) * CINc : 0;
        meta[t] = m;
    }
    __syncthreads();

    float acc[4][2][4];
    #pragma unroll
    for (int mt = 0; mt < 4; mt++)
        #pragma unroll
        for (int nt = 0; nt < 2; nt++)
            #pragma unroll
            for (int r = 0; r < 4; r++) acc[mt][nt][r] = 0.f;

    const int bpix = tid >> 2, bchq = tid & 3;   // 64 pixels x 4 chunk-quarters

    uint4 bufA[4];          // A: 128 rows x 8 uint4 = 1024 / 256 thr
    uint4 cb[4][2];
    __half2 w0h, w1h, w2h, w3h;

    auto ldg_chunk = [&](int i) {
        #pragma unroll
        for (int m = 0; m < 4; m++) {
            int e = tid + m * 256;
            bufA[m] = *(const uint4*)(g_wtp + (size_t)i * 8192 + e * 8);
        }
        int kk = i >> 1;
        MetaF m = meta[kk * TILE_N + bpix];
        w0h = __float2half2_rn(m.w0);
        w1h = __float2half2_rn(m.w1);
        w2h = __float2half2_rn(m.w2);
        w3h = __float2half2_rn(m.w3);
        const __half* base = xhb + (i & 1) * 64 + bchq * 16;
        cb[0][0] = *(const uint4*)(base + m.i0);
        cb[0][1] = *(const uint4*)(base + m.i0 + 8);
        cb[1][0] = *(const uint4*)(base + m.i1);
        cb[1][1] = *(const uint4*)(base + m.i1 + 8);
        cb[2][0] = *(const uint4*)(base + m.i2);
        cb[2][1] = *(const uint4*)(base + m.i2 + 8);
        cb[3][0] = *(const uint4*)(base + m.i3);
        cb[3][1] = *(const uint4*)(base + m.i3 + 8);
    };
    auto sts_chunk = [&](int st) {
        __half* As = smh + st * GSTG_H;
        __half* Bs = As + GA_H;
        #pragma unroll
        for (int m = 0; m < 4; m++) {
            int e = tid + m * 256;
            *(uint4*)(As + (e >> 3) * SRH + (e & 7) * 8) = bufA[m];
        }
        uint4 o0, o1;
        o0.x = blend4h(cb[0][0].x, cb[1][0].x, cb[2][0].x, cb[3][0].x, w0h, w1h, w2h, w3h);
        o0.y = blend4h(cb[0][0].y, cb[1][0].y, cb[2][0].y, cb[3][0].y, w0h, w1h, w2h, w3h);
        o0.z = blend4h(cb[0][0].z, cb[1][0].z, cb[2][0].z, cb[3][0].z, w0h, w1h, w2h, w3h);
        o0.w = blend4h(cb[0][0].w, cb[1][0].w, cb[2][0].w, cb[3][0].w, w0h, w1h, w2h, w3h);
        o1.x = blend4h(cb[0][1].x, cb[1][1].x, cb[2][1].x, cb[3][1].x, w0h, w1h, w2h, w3h);
        o1.y = blend4h(cb[0][1].y, cb[1][1].y, cb[2][1].y, cb[3][1].y, w0h, w1h, w2h, w3h);
        o1.z = blend4h(cb[0][1].z, cb[1][1].z, cb[2][1].z, cb[3][1].z, w0h, w1h, w2h, w3h);
        o1.w = blend4h(cb[0][1].w, cb[1][1].w, cb[2][1].w, cb[3][1].w, w0h, w1h, w2h, w3h);
        *(uint4*)(Bs + bpix * SRH + bchq * 16) = o0;
        *(uint4*)(Bs + bpix * SRH + bchq * 16 + 8) = o1;
    };

    ldg_chunk(0); sts_chunk(0);
    ldg_chunk(1);
    __syncthreads();

    for (int i = 0; i < NCH64; i++) {
        if (i + 1 < NCH64) sts_chunk((i + 1) & 1);
        if (i + 2 < NCH64) ldg_chunk(i + 2);

        const uint32_t aAs = sbase + (uint32_t)((i & 1) * GSTG_H) * 2;
        const uint32_t aBs = aAs + GA_H * 2;
        #pragma unroll
        for (int ks = 0; ks < 4; ks++) {
            uint32_t a[4][4];
            #pragma unroll
            for (int mt = 0; mt < 4; mt++)
                ldsm_x4(a[mt], aAs + (uint32_t)((wm * 64 + mt * 16) * SRH + ks * 16) * 2 + laneA);
            #pragma unroll
            for (int nt = 0; nt < 2; nt++) {
                uint32_t b0, b1;
                ldsm_x2(b0, b1, aBs + (uint32_t)((wn * 16 + nt * 8) * SRH + ks * 16) * 2 + laneB);
                #pragma unroll
                for (int mt = 0; mt < 4; mt++)
                    mma_f16(acc[mt][nt], a[mt], b0, b1);
            }
        }
        __syncthreads();
    }

    // ---- store results ----
    #pragma unroll
    for (int mt = 0; mt < 4; mt++) {
        #pragma unroll
        for (int nt = 0; nt < 2; nt++) {
            int pix = hw0 + wn * 16 + nt * 8 + tc * 2;
            int co0 = wm * 64 + mt * 16 + g;
            *(float2*)&out[((size_t)b * COUTc + co0) * HWn + pix] =
                make_float2(acc[mt][nt][0], acc[mt][nt][1]);
            *(float2*)&out[((size_t)b * COUTc + co0 + 8) * HWn + pix] =
                make_float2(acc[mt][nt][2], acc[mt][nt][3]);
        }
    }

    // ---- deterministic BN partials ----
    float s[8], q[8];
    #pragma unroll
    for (int i = 0; i < 8; i++) { s[i] = 0.f; q[i] = 0.f; }
    #pragma unroll
    for (int mt = 0; mt < 4; mt++)
        #pragma unroll
        for (int r = 0; r < 2; r++) {
            int sl = mt * 2 + r;
            #pragma unroll
            for (int nt = 0; nt < 2; nt++) {
                float v0 = acc[mt][nt][r * 2], v1 = acc[mt][nt][r * 2 + 1];
                s[sl] += v0 + v1;
                q[sl] += v0 * v0 + v1 * v1;
            }
        }
    #pragma unroll
    for (int m = 1; m <= 2; m <<= 1)
        #pragma unroll
        for (int i = 0; i < 8; i++) {
            s[i] += __shfl_xor_sync(0xFFFFFFFF, s[i], m);
            q[i] += __shfl_xor_sync(0xFFFFFFFF, q[i], m);
        }

    __syncthreads();
    float* sb = (float*)smraw;          // [8 warps][64]
    float* qb = sb + 512;
    if (tc == 0) {
        #pragma unroll
        for (int mt = 0; mt < 4; mt++)
            #pragma unroll
            for (int r = 0; r < 2; r++) {
                int cl = mt * 16 + r * 8 + g;
                sb[wid * 64 + cl] = s[mt * 2 + r];
                qb[wid * 64 + cl] = q[mt * 2 + r];
            }
    }
    __syncthreads();
    if (tid < COUTc) {
        int co = tid;
        float ss = 0.f, qq = 0.f;
        #pragma unroll
        for (int w = 0; w < 4; w++) {
            int widx = (co >> 6) * 4 + w;    // warps with matching wm
            ss += sb[widx * 64 + (co & 63)];
            qq += qb[widx * 64 + (co & 63)];
        }
        g_psum[co * NTILES + blockIdx.x] = ss;
        g_psq [co * NTILES + blockIdx.x] = qq;
    }
}

// ---------------------------------------------------------------------------
// Kernel 4: fused BN-finalize + normalize + SiLU. 1024 CTAs, 4 float4/thread.
// 512 partials per channel: each thread sums 2, then block-reduce.
// ---------------------------------------------------------------------------
__global__ __launch_bounds__(256) void k_norm(float* __restrict__ out,
                                              const float* __restrict__ gamma,
                                              const float* __restrict__ beta) {
    __shared__ float rs[8], rq[8];
    __shared__ float bc[2];
    const int n4 = Bn * COUTc * HWn / 4;   // 1048576
    const int qn = n4 / 4;                 // 262144
    const int tid = threadIdx.x;
    const int idx = blockIdx.x * 256 + tid;
    const int co  = (idx >> 10) & 127;     // constant across the CTA
    float4* o4 = (float4*)out;

    // prefetch all four quarters (overlaps the reduction below)
    float4 v0 = o4[idx];
    float4 v1 = o4[idx + qn];
    float4 v2 = o4[idx + 2 * qn];
    float4 v3 = o4[idx + 3 * qn];

    // block-reduce this channel's 512 partials
    float s = g_psum[co * NTILES + tid] + g_psum[co * NTILES + 256 + tid];
    float q = g_psq [co * NTILES + tid] + g_psq [co * NTILES + 256 + tid];
    #pragma unroll
    for (int m = 16; m > 0; m >>= 1) {
        s += __shfl_xor_sync(0xFFFFFFFF, s, m);
        q += __shfl_xor_sync(0xFFFFFFFF, q, m);
    }
    if ((tid & 31) == 0) { rs[tid >> 5] = s; rq[tid >> 5] = q; }
    __syncthreads();
    if (tid == 0) {
        float ss = 0.f, qq = 0.f;
        #pragma unroll
        for (int w = 0; w < 8; w++) { ss += rs[w]; qq += rq[w]; }
        const float inv_n = 1.f / (float)NPIX;
        float mean = ss * inv_n;
        float var  = qq * inv_n - mean * mean;
        float sc   = gamma[co] * rsqrtf(var + 1e-5f);
        bc[0] = sc;
        bc[1] = beta[co] - mean * sc;
    }
    __syncthreads();
    const float sc = bc[0], sh = bc[1];

    v0.x = silu_f(v0.x * sc + sh); v0.y = silu_f(v0.y * sc + sh);
    v0.z = silu_f(v0.z * sc + sh); v0.w = silu_f(v0.w * sc + sh);
    v1.x = silu_f(v1.x * sc + sh); v1.y = silu_f(v1.y * sc + sh);
    v1.z = silu_f(v1.z * sc + sh); v1.w = silu_f(v1.w * sc + sh);
    v2.x = silu_f(v2.x * sc + sh); v2.y = silu_f(v2.y * sc + sh);
    v2.z = silu_f(v2.z * sc + sh); v2.w = silu_f(v2.w * sc + sh);
    v3.x = silu_f(v3.x * sc + sh); v3.y = silu_f(v3.y * sc + sh);
    v3.z = silu_f(v3.z * sc + sh); v3.w = silu_f(v3.w * sc + sh);

    o4[idx] = v0;
    o4[idx + qn] = v1;
    o4[idx + 2 * qn] = v2;
    o4[idx + 3 * qn] = v3;
}

// ---------------------------------------------------------------------------
extern "C" void kernel_launch(void* const* d_in, const int* in_sizes, int n_in,
                              void* d_out, int out_size) {
    const float* x     = (const float*)d_in[0];
    const float* w_off = (const float*)d_in[1];
    const float* w_def = (const float*)d_in[2];
    // d_in[3] = b_def: exactly absorbed by batch-norm mean subtraction
    const float* gamma = (const float*)d_in[4];
    const float* beta  = (const float*)d_in[5];
    float* out = (float*)d_out;

    cudaFuncSetAttribute(k_gemm, cudaFuncAttributeMaxDynamicSharedMemorySize, GEMM_SMEM);
    cudaFuncSetAttribute(k_offset2, cudaFuncAttributeMaxDynamicSharedMemorySize, OFF_SMEM);

    k_prep<<<4096 + (NCH64 * 10240 + 255) / 256, 256>>>(x, w_def, w_off);

    k_offset2<<<512, 256, OFF_SMEM>>>();

    k_gemm<<<NTILES, 256, GEMM_SMEM>>>(out);

    k_norm<<<(Bn * COUTc * HWn / 4) / 1024, 256>>>(out, gamma, beta);
}

// round 17
// speedup vs baseline: 1.0370x; 1.0370x over previous
#include <cuda_runtime.h>
#include <cuda_fp16.h>
#include <math.h>
#include <stdint.h>

#define Bn 8
#define CINc 128
#define COUTc 128
#define Hh 64
#define Ww 64
#define HWn 4096
#define KKn 9
#define OFFC 18
#define Kdim 1152            // CIN * KK
#define NPIX 32768           // B * HW
#define TILE_N 128           // pixels per fused-GEMM CTA
#define NCH64 18             // Kdim / 64
#define SRH 72               // smem row stride in halves (64 + pad 8)

// fused gemm smem: 2 stages of (A 128x72 + B 128x72) halves + meta
#define GA_H (128 * SRH)             // 9216 halves
#define GB_H (128 * SRH)             // 9216
#define GSTG_H (GA_H + GB_H)         // 18432
#define META_BYTES (KKn * 128 * 32)  // 36864
#define GEMM_SMEM (2 * GSTG_H * 2 + META_BYTES)   // 110592 B

// offset phase (inside k_gemm): A 32x72, B 128x72 per stage (fits in GSTG_H)
#define OFA_H (32 * SRH)             // 2304
#define OFB_H (128 * SRH)            // 9216

// ---------------- static scratch ----------------
__device__ __half g_xh[Bn * HWn * CINc];     // x NHWC fp16 (8.4 MB)
__device__ __half g_wtp[NCH64 * 8192];       // w_def packed [ch64][co][64k]
__device__ __half g_woffp[NCH64 * 2048];     // w_off packed [ch64][oc32][64k]
__device__ float  g_psum[COUTc * 256];
__device__ float  g_psq [COUTc * 256];

// ---------------- helpers ----------------
__device__ __forceinline__ void mma_f16(float* d, const uint32_t* a,
                                        uint32_t b0, uint32_t b1) {
    asm volatile(
        "mma.sync.aligned.m16n8k16.row.col.f32.f16.f16.f32 "
        "{%0,%1,%2,%3}, {%4,%5,%6,%7}, {%8,%9}, {%0,%1,%2,%3};"
        : "+f"(d[0]), "+f"(d[1]), "+f"(d[2]), "+f"(d[3])
        : "r"(a[0]), "r"(a[1]), "r"(a[2]), "r"(a[3]), "r"(b0), "r"(b1));
}
__device__ __forceinline__ void ldsm_x4(uint32_t* r, uint32_t addr) {
    asm volatile("ldmatrix.sync.aligned.m8n8.x4.shared.b16 {%0,%1,%2,%3}, [%4];"
                 : "=r"(r[0]), "=r"(r[1]), "=r"(r[2]), "=r"(r[3]) : "r"(addr));
}
__device__ __forceinline__ void ldsm_x2(uint32_t& r0, uint32_t& r1, uint32_t addr) {
    asm volatile("ldmatrix.sync.aligned.m8n8.x2.shared.b16 {%0,%1}, [%2];"
                 : "=r"(r0), "=r"(r1) : "r"(addr));
}
__device__ __forceinline__ uint32_t s2u(const void* p) {
    return (uint32_t)__cvta_generic_to_shared(p);
}
// pure-fp16 bilinear blend (HMUL2/HFMA2, no cvts)
__device__ __forceinline__ uint32_t blend4h(uint32_t a, uint32_t b,
                                            uint32_t c, uint32_t d,
                                            __half2 w0, __half2 w1,
                                            __half2 w2, __half2 w3) {
    __half2 r = __hmul2(*(__half2*)&a, w0);
    r = __hfma2(*(__half2*)&b, w1, r);
    r = __hfma2(*(__half2*)&c, w2, r);
    r = __hfma2(*(__half2*)&d, w3, r);
    return *(uint32_t*)&r;
}
__device__ __forceinline__ float silu_f(float u) {
    return __fdividef(u, 1.f + __expf(-u));
}

struct __align__(16) MetaF {
    int   i0, i1, i2, i3;
    float w0, w1, w2, w3;
};

// lane offsets for ldmatrix source rows (in BYTES)
#define LANE_OFF_A(lane) ((((lane) & 15) * SRH + (((lane) >> 4) << 3)) * 2)
#define LANE_OFF_B(lane) ((((lane) & 7) * SRH + ((((lane) >> 3) & 1) << 3)) * 2)

// ---------------------------------------------------------------------------
// Kernel 1: merged prep — blocks [0,4096): NCHW->NHWC fp16 transpose,
//           blocks [4096,4816): weight packs
// ---------------------------------------------------------------------------
__global__ __launch_bounds__(256) void k_prep(const float* __restrict__ x,
                                              const float* __restrict__ w_def,
                                              const float* __restrict__ w_off) {
    int bid = blockIdx.x;
    int tid = threadIdx.x;
    if (bid < 4096) {
        __shared__ float tile[32][33];
        int p0 = (bid & 127) * 32;
        int c0 = ((bid >> 7) & 3) * 32;
        int b  = bid >> 9;
        const float* xb = x + (size_t)b * CINc * HWn;
        __half* xtb = g_xh + (size_t)b * HWn * CINc;
        int tx = tid & 31, ty = tid >> 5;
        #pragma unroll
        for (int j = 0; j < 32; j += 8)
            tile[ty + j][tx] = xb[(size_t)(c0 + ty + j) * HWn + p0 + tx];
        __syncthreads();
        #pragma unroll
        for (int m = 0; m < 2; m++) {
            int u = tid + m * 256;
            int pl = u >> 4, cp = u & 15;
            __half2 v = __floats2half2_rn(tile[cp * 2][pl], tile[cp * 2 + 1][pl]);
            *(__half2*)(xtb + (size_t)(p0 + pl) * CINc + c0 + cp * 2) = v;
        }
    } else {
        int idx = (bid - 4096) * 256 + tid;
        if (idx < NCH64 * 8192) {
            int chunk = idx >> 13, r = idx & 8191;
            int co = r >> 6, kloc = r & 63;
            int k = chunk * 64 + kloc;
            int kk = k >> 7, c = k & 127;
            g_wtp[idx] = __float2half(w_def[(size_t)(co * CINc + c) * KKn + kk]);
        } else {
            int j = idx - NCH64 * 8192;
            if (j < NCH64 * 2048) {
                int chunk = j >> 11, r = j & 2047;
                int oc = r >> 6, kloc = r & 63;
                int kk = chunk >> 1, c = (chunk & 1) * 64 + kloc;
                g_woffp[j] = (oc < OFFC)
                    ? __float2half(w_off[(size_t)(oc * CINc + c) * KKn + kk])
                    : __float2half(0.f);
            }
        }
    }
}

// ---------------------------------------------------------------------------
// Kernel 2: MEGA-FUSED  offset-conv + bilinear-gather + main fp16 GEMM.
// 256 CTAs x 512 thr. Phase A: offset conv (18ch x 128pix) into smem.
// Phase B: bilinear meta from smem offsets. Phase C: main 128x128 GEMM.
// ---------------------------------------------------------------------------
__global__ __launch_bounds__(512, 1) void k_gemm(float* __restrict__ out) {
    extern __shared__ char smraw[];
    __half* smh  = (__half*)smraw;
    MetaF*  meta = (MetaF*)(smraw + 2 * GSTG_H * 2);

    const int tid = threadIdx.x;
    const int wid = tid >> 5, lane = tid & 31;
    const int wm = wid >> 3, wn = wid & 7;
    const int g = lane >> 2, tc = lane & 3;
    const int tilebase = blockIdx.x * TILE_N;
    const int b = tilebase >> 12, hw0 = tilebase & 4095;
    const int ybase = hw0 >> 6;               // 2 rows of 64 per tile
    const __half* xhb = g_xh + (size_t)b * HWn * CINc;

    const uint32_t sbase = s2u(smh);
    const uint32_t laneA = LANE_OFF_A(lane);
    const uint32_t laneB = LANE_OFF_B(lane);

    // ======== phase A: offset conv for this tile's 128 pixels ========
    {
        float oacc[2][4];
        #pragma unroll
        for (int mt = 0; mt < 2; mt++)
            #pragma unroll
            for (int r = 0; r < 4; r++) oacc[mt][r] = 0.f;

        uint4 obB[2];
        uint4 obA;

        auto oldg = [&](int i) {
            int kk = i >> 1, c0 = (i & 1) * 64;
            int ky = kk / 3 - 1, kx = kk % 3 - 1;
            #pragma unroll
            for (int m = 0; m < 2; m++) {
                int e = tid + m * 512;
                int pix = e >> 3, j = e & 7;
                int y = ybase + (pix >> 6), xx = pix & 63;
                int ys = y + ky, xs = xx + kx;
                bool valid = ((unsigned)ys < Hh) && ((unsigned)xs < Ww);
                obB[m] = valid
                    ? *(const uint4*)(xhb + (size_t)(ys * Ww + xs) * CINc + c0 + j * 8)
                    : make_uint4(0u, 0u, 0u, 0u);
            }
            if (tid < 256)
                obA = *(const uint4*)(g_woffp + (size_t)i * 2048 + tid * 8);
        };
        auto osts = [&](int st) {
            __half* As = smh + st * GSTG_H;
            __half* Bs = As + OFA_H;
            #pragma unroll
            for (int m = 0; m < 2; m++) {
                int e = tid + m * 512;
                int pix = e >> 3, j = e & 7;
                *(uint4*)(Bs + pix * SRH + j * 8) = obB[m];
            }
            if (tid < 256)
                *(uint4*)(As + (tid >> 3) * SRH + (tid & 7) * 8) = obA;
        };

        oldg(0); osts(0);
        oldg(1);
        __syncthreads();

        for (int i = 0; i < NCH64; i++) {
            if (i + 1 < NCH64) osts((i + 1) & 1);
            if (i + 2 < NCH64) oldg(i + 2);
            const uint32_t aAs = sbase + (uint32_t)((i & 1) * GSTG_H) * 2;
            const uint32_t aBs = aAs + OFA_H * 2;
            #pragma unroll
            for (int ks = 0; ks < 4; ks++) {
                uint32_t a[2][4];
                #pragma unroll
                for (int mt = 0; mt < 2; mt++)
                    ldsm_x4(a[mt], aAs + (uint32_t)((mt * 16) * SRH + ks * 16) * 2 + laneA);
                uint32_t b0, b1;
                ldsm_x2(b0, b1, aBs + (uint32_t)((wid * 8) * SRH + ks * 16) * 2 + laneB);
                #pragma unroll
                for (int mt = 0; mt < 2; mt++)
                    mma_f16(oacc[mt], a[mt], b0, b1);
            }
            __syncthreads();
        }

        // store 18 x 128 offsets to smem (overlays stage area; meta reads next)
        float* offsm = (float*)smh;     // [18][128] floats = 9216 B
        int pix = wid * 8 + tc * 2;
        #pragma unroll
        for (int mt = 0; mt < 2; mt++) {
            int r0 = mt * 16 + g, r1 = r0 + 8;
            if (r0 < OFFC)
                *(float2*)&offsm[r0 * 128 + pix] = make_float2(oacc[mt][0], oacc[mt][1]);
            if (r1 < OFFC)
                *(float2*)&offsm[r1 * 128 + pix] = make_float2(oacc[mt][2], oacc[mt][3]);
        }
    }
    __syncthreads();

    // ======== phase B: bilinear metadata from smem offsets ========
    {
        const float* offsm = (const float*)smh;
        for (int t = tid; t < KKn * 128; t += 512) {
            int kk = t >> 7, p = t & 127;
            int xx = (hw0 + p) & 63;
            int y = ybase + (p >> 6);
            float dy = offsm[(kk * 2 + 0) * 128 + p];
            float dx = offsm[(kk * 2 + 1) * 128 + p];
            float ys = (float)(y - 1 + kk / 3) + dy;
            float xs = (float)(xx - 1 + kk % 3) + dx;
            float y0f = floorf(ys), x0f = floorf(xs);
            float wy = ys - y0f, wx = xs - x0f;
            int y0 = (int)y0f, x0 = (int)x0f;
            bool vy0 = (y0 >= 0) && (y0 < Hh);
            bool vy1 = (y0 + 1 >= 0) && (y0 + 1 < Hh);
            bool vx0 = (x0 >= 0) && (x0 < Ww);
            bool vx1 = (x0 + 1 >= 0) && (x0 + 1 < Ww);
            MetaF m;
            m.w0 = (vy0 && vx0) ? (1.f - wy) * (1.f - wx) : 0.f;
            m.w1 = (vy0 && vx1) ? (1.f - wy) * wx : 0.f;
            m.w2 = (vy1 && vx0) ? wy * (1.f - wx) : 0.f;
            m.w3 = (vy1 && vx1) ? wy * wx : 0.f;
            m.i0 = (vy0 && vx0) ? (y0 * Ww + x0) * CINc : 0;
            m.i1 = (vy0 && vx1) ? (y0 * Ww + x0 + 1) * CINc : 0;
            m.i2 = (vy1 && vx0) ? ((y0 + 1) * Ww + x0) * CINc : 0;
            m.i3 = (vy1 && vx1) ? ((y0 + 1) * Ww + x0 + 1) * CINc : 0;
            meta[t] = m;
        }
    }
    __syncthreads();

    // ======== phase C: main fused gather+GEMM ========
    float acc[4][2][4];
    #pragma unroll
    for (int mt = 0; mt < 4; mt++)
        #pragma unroll
        for (int nt = 0; nt < 2; nt++)
            #pragma unroll
            for (int r = 0; r < 4; r++) acc[mt][nt][r] = 0.f;

    const int bpix = tid >> 2, bchq = tid & 3;

    uint4 bufA[2];
    uint4 cb[4][2];
    __half2 w0h, w1h, w2h, w3h;

    auto ldg_chunk = [&](int i) {
        #pragma unroll
        for (int m = 0; m < 2; m++) {
            int e = tid + m * 512;
            bufA[m] = *(const uint4*)(g_wtp + (size_t)i * 8192 + e * 8);
        }
        int kk = i >> 1;
        MetaF m = meta[kk * 128 + bpix];
        w0h = __float2half2_rn(m.w0);
        w1h = __float2half2_rn(m.w1);
        w2h = __float2half2_rn(m.w2);
        w3h = __float2half2_rn(m.w3);
        const __half* base = xhb + (i & 1) * 64 + bchq * 16;
        cb[0][0] = *(const uint4*)(base + m.i0);
        cb[0][1] = *(const uint4*)(base + m.i0 + 8);
        cb[1][0] = *(const uint4*)(base + m.i1);
        cb[1][1] = *(const uint4*)(base + m.i1 + 8);
        cb[2][0] = *(const uint4*)(base + m.i2);
        cb[2][1] = *(const uint4*)(base + m.i2 + 8);
        cb[3][0] = *(const uint4*)(base + m.i3);
        cb[3][1] = *(const uint4*)(base + m.i3 + 8);
    };
    auto sts_chunk = [&](int st) {
        __half* As = smh + st * GSTG_H;
        __half* Bs = As + GA_H;
        #pragma unroll
        for (int m = 0; m < 2; m++) {
            int e = tid + m * 512;
            *(uint4*)(As + (e >> 3) * SRH + (e & 7) * 8) = bufA[m];
        }
        uint4 o0, o1;
        o0.x = blend4h(cb[0][0].x, cb[1][0].x, cb[2][0].x, cb[3][0].x, w0h, w1h, w2h, w3h);
        o0.y = blend4h(cb[0][0].y, cb[1][0].y, cb[2][0].y, cb[3][0].y, w0h, w1h, w2h, w3h);
        o0.z = blend4h(cb[0][0].z, cb[1][0].z, cb[2][0].z, cb[3][0].z, w0h, w1h, w2h, w3h);
        o0.w = blend4h(cb[0][0].w, cb[1][0].w, cb[2][0].w, cb[3][0].w, w0h, w1h, w2h, w3h);
        o1.x = blend4h(cb[0][1].x, cb[1][1].x, cb[2][1].x, cb[3][1].x, w0h, w1h, w2h, w3h);
        o1.y = blend4h(cb[0][1].y, cb[1][1].y, cb[2][1].y, cb[3][1].y, w0h, w1h, w2h, w3h);
        o1.z = blend4h(cb[0][1].z, cb[1][1].z, cb[2][1].z, cb[3][1].z, w0h, w1h, w2h, w3h);
        o1.w = blend4h(cb[0][1].w, cb[1][1].w, cb[2][1].w, cb[3][1].w, w0h, w1h, w2h, w3h);
        *(uint4*)(Bs + bpix * SRH + bchq * 16) = o0;
        *(uint4*)(Bs + bpix * SRH + bchq * 16 + 8) = o1;
    };

    ldg_chunk(0); sts_chunk(0);
    ldg_chunk(1);
    __syncthreads();

    for (int i = 0; i < NCH64; i++) {
        if (i + 1 < NCH64) sts_chunk((i + 1) & 1);
        if (i + 2 < NCH64) ldg_chunk(i + 2);

        const uint32_t aAs = sbase + (uint32_t)((i & 1) * GSTG_H) * 2;
        const uint32_t aBs = aAs + GA_H * 2;
        #pragma unroll
        for (int ks = 0; ks < 4; ks++) {
            uint32_t a[4][4];
            #pragma unroll
            for (int mt = 0; mt < 4; mt++)
                ldsm_x4(a[mt], aAs + (uint32_t)((wm * 64 + mt * 16) * SRH + ks * 16) * 2 + laneA);
            #pragma unroll
            for (int nt = 0; nt < 2; nt++) {
                uint32_t b0, b1;
                ldsm_x2(b0, b1, aBs + (uint32_t)((wn * 16 + nt * 8) * SRH + ks * 16) * 2 + laneB);
                #pragma unroll
                for (int mt = 0; mt < 4; mt++)
                    mma_f16(acc[mt][nt], a[mt], b0, b1);
            }
        }
        __syncthreads();
    }

    // ---- store results ----
    #pragma unroll
    for (int mt = 0; mt < 4; mt++) {
        #pragma unroll
        for (int nt = 0; nt < 2; nt++) {
            int pix = hw0 + wn * 16 + nt * 8 + tc * 2;
            int co0 = wm * 64 + mt * 16 + g;
            *(float2*)&out[((size_t)b * COUTc + co0) * HWn + pix] =
                make_float2(acc[mt][nt][0], acc[mt][nt][1]);
            *(float2*)&out[((size_t)b * COUTc + co0 + 8) * HWn + pix] =
                make_float2(acc[mt][nt][2], acc[mt][nt][3]);
        }
    }

    // ---- deterministic BN partials ----
    float s[8], q[8];
    #pragma unroll
    for (int i = 0; i < 8; i++) { s[i] = 0.f; q[i] = 0.f; }
    #pragma unroll
    for (int mt = 0; mt < 4; mt++)
        #pragma unroll
        for (int r = 0; r < 2; r++) {
            int sl = mt * 2 + r;
            #pragma unroll
            for (int nt = 0; nt < 2; nt++) {
                float v0 = acc[mt][nt][r * 2], v1 = acc[mt][nt][r * 2 + 1];
                s[sl] += v0 + v1;
                q[sl] += v0 * v0 + v1 * v1;
            }
        }
    #pragma unroll
    for (int m = 1; m <= 2; m <<= 1)
        #pragma unroll
        for (int i = 0; i < 8; i++) {
            s[i] += __shfl_xor_sync(0xFFFFFFFF, s[i], m);
            q[i] += __shfl_xor_sync(0xFFFFFFFF, q[i], m);
        }

    __syncthreads();
    float* sb = (float*)smraw;
    float* qb = sb + 1024;
    if (tc == 0) {
        #pragma unroll
        for (int mt = 0; mt < 4; mt++)
            #pragma unroll
            for (int r = 0; r < 2; r++) {
                int cl = mt * 16 + r * 8 + g;
                sb[wid * 64 + cl] = s[mt * 2 + r];
                qb[wid * 64 + cl] = q[mt * 2 + r];
            }
    }
    __syncthreads();
    if (tid < COUTc) {
        int co = tid;
        float ss = 0.f, qq = 0.f;
        #pragma unroll
        for (int w = 0; w < 8; w++) {
            ss += sb[((co >> 6) * 8 + w) * 64 + (co & 63)];
            qq += qb[((co >> 6) * 8 + w) * 64 + (co & 63)];
        }
        g_psum[co * 256 + blockIdx.x] = ss;
        g_psq [co * 256 + blockIdx.x] = qq;
    }
}

// ---------------------------------------------------------------------------
// Kernel 3: fused BN-finalize + normalize + SiLU. 1024 CTAs, 4 float4/thread.
// ---------------------------------------------------------------------------
__global__ __launch_bounds__(256) void k_norm(float* __restrict__ out,
                                              const float* __restrict__ gamma,
                                              const float* __restrict__ beta) {
    __shared__ float rs[8], rq[8];
    __shared__ float bc[2];
    const int n4 = Bn * COUTc * HWn / 4;   // 1048576
    const int qn = n4 / 4;                 // 262144
    const int tid = threadIdx.x;
    const int idx = blockIdx.x * 256 + tid;
    const int co  = (idx >> 10) & 127;     // constant across the CTA
    float4* o4 = (float4*)out;

    float4 v0 = o4[idx];
    float4 v1 = o4[idx + qn];
    float4 v2 = o4[idx + 2 * qn];
    float4 v3 = o4[idx + 3 * qn];

    float s = g_psum[co * 256 + tid];
    float q = g_psq [co * 256 + tid];
    #pragma unroll
    for (int m = 16; m > 0; m >>= 1) {
        s += __shfl_xor_sync(0xFFFFFFFF, s, m);
        q += __shfl_xor_sync(0xFFFFFFFF, q, m);
    }
    if ((tid & 31) == 0) { rs[tid >> 5] = s; rq[tid >> 5] = q; }
    __syncthreads();
    if (tid == 0) {
        float ss = 0.f, qq = 0.f;
        #pragma unroll
        for (int w = 0; w < 8; w++) { ss += rs[w]; qq += rq[w]; }
        const float inv_n = 1.f / (float)NPIX;
        float mean = ss * inv_n;
        float var  = qq * inv_n - mean * mean;
        float sc   = gamma[co] * rsqrtf(var + 1e-5f);
        bc[0] = sc;
        bc[1] = beta[co] - mean * sc;
    }
    __syncthreads();
    const float sc = bc[0], sh = bc[1];

    v0.x = silu_f(v0.x * sc + sh); v0.y = silu_f(v0.y * sc + sh);
    v0.z = silu_f(v0.z * sc + sh); v0.w = silu_f(v0.w * sc + sh);
    v1.x = silu_f(v1.x * sc + sh); v1.y = silu_f(v1.y * sc + sh);
    v1.z = silu_f(v1.z * sc + sh); v1.w = silu_f(v1.w * sc + sh);
    v2.x = silu_f(v2.x * sc + sh); v2.y = silu_f(v2.y * sc + sh);
    v2.z = silu_f(v2.z * sc + sh); v2.w = silu_f(v2.w * sc + sh);
    v3.x = silu_f(v3.x * sc + sh); v3.y = silu_f(v3.y * sc + sh);
    v3.z = silu_f(v3.z * sc + sh); v3.w = silu_f(v3.w * sc + sh);

    o4[idx] = v0;
    o4[idx + qn] = v1;
    o4[idx + 2 * qn] = v2;
    o4[idx + 3 * qn] = v3;
}

// ---------------------------------------------------------------------------
extern "C" void kernel_launch(void* const* d_in, const int* in_sizes, int n_in,
                              void* d_out, int out_size) {
    const float* x     = (const float*)d_in[0];
    const float* w_off = (const float*)d_in[1];
    const float* w_def = (const float*)d_in[2];
    // d_in[3] = b_def: exactly absorbed by batch-norm mean subtraction
    const float* gamma = (const float*)d_in[4];
    const float* beta  = (const float*)d_in[5];
    float* out = (float*)d_out;

    cudaFuncSetAttribute(k_gemm, cudaFuncAttributeMaxDynamicSharedMemorySize, GEMM_SMEM);

    k_prep<<<4096 + (NCH64 * 10240 + 255) / 256, 256>>>(x, w_def, w_off);

    k_gemm<<<NPIX / TILE_N, 512, GEMM_SMEM>>>(out);

    k_norm<<<(Bn * COUTc * HWn / 4) / 1024, 256>>>(out, gamma, beta);
}